// round 7
// baseline (speedup 1.0000x reference)
#include <cuda_runtime.h>
#include <cuda_bf16.h>
#include <math.h>

#define B_    128
#define Q_    16
#define D_    1024
#define E_    300
#define K_    11
#define CTAS_PER_B 8
#define DOCS_PER_CTA (D_/CTAS_PER_B)   // 128
#define THREADS1 128
#define E4    (E_/4)                   // 75 float4
#define HSTEP 38                       // f4 steps per half (38 + 37, padded)
#define QSTRIDE 304                    // floats (76 f4, pad f4 zeroed)
#define Q4S   (QSTRIDE/4)
#define SSTRIDE 136                    // mod 32 == 8 -> conflict-free RBF reads

// partials: [1024 CTAs][16 q][13] (11 kacc + 1 simacc + pad)
__device__ float g_part[B_*CTAS_PER_B*Q_*13];
__device__ int   g_count[B_];          // zero-init; reset by last CTA each run

__global__ __launch_bounds__(THREADS1, 7)
void knrm_part_kernel(const int* __restrict__ doctoks,
                      const int* __restrict__ querytoks,
                      const float* __restrict__ emb,
                      const float* __restrict__ mus,
                      const float* __restrict__ sigmas,
                      const float* __restrict__ fc_w,
                      const float* __restrict__ fc_b,
                      float* __restrict__ out)
{
    __shared__ float qn[Q_*QSTRIDE];       // 16 x 304 (e 300..303 zeroed)
    __shared__ float s_sh[Q_*SSTRIDE];     // 16 x 136
    __shared__ float tmp16[16];
    __shared__ int last_flag;

    const int tid  = threadIdx.x;
    const int b    = blockIdx.x >> 3;
    const int cta  = blockIdx.x & 7;
    const int wid  = tid >> 5;
    const int lane = tid & 31;
    const int l16  = lane & 15;            // doc slot within warp
    const int half = lane >> 4;            // 0: e[0,152), 1: e[152,300)

    // ---- load + normalize query embeddings into shared ----
    for (int i = tid; i < Q_*E_; i += THREADS1) {
        int q = i / E_, e = i - q*E_;
        int t = querytoks[b*Q_ + q];
        qn[q*QSTRIDE + e] = emb[t*E_ + e];
    }
    if (tid < Q_*4) {                      // zero the pad float4 of each row
        int q = tid >> 2;
        qn[q*QSTRIDE + E_ + (tid & 3)] = 0.f;
    }
    __syncthreads();
    {
        int q = tid >> 3, l = tid & 7;     // 16 q-rows x 8 lanes
        float ss = 0.f;
        for (int e = l; e < E_; e += 8) { float v = qn[q*QSTRIDE + e]; ss += v*v; }
        #pragma unroll
        for (int o = 4; o > 0; o >>= 1) ss += __shfl_down_sync(0xffffffffu, ss, o, 8);
        if (l == 0) tmp16[q] = 1.0f / (sqrtf(ss) + 1e-9f);
    }
    __syncthreads();
    for (int i = tid; i < Q_*E_; i += THREADS1) {
        int q = i / E_, e = i - q*E_;
        qn[q*QSTRIDE + e] *= tmp16[q];
    }
    __syncthreads();

    // ---- dot products: 2 docs/thread, E split across half-warps ----
    const int dpos0 = wid*32 + l16;        // this thread's doc (and +16)
    const int t0 = doctoks[b*D_ + cta*DOCS_PER_CTA + dpos0];
    const int t1 = doctoks[b*D_ + cta*DOCS_PER_CTA + dpos0 + 16];
    const float4* p0 = reinterpret_cast<const float4*>(emb) + (long)t0 * E4;
    const float4* p1 = reinterpret_cast<const float4*>(emb) + (long)t1 * E4;
    const float4* qn4 = reinterpret_cast<const float4*>(qn);
    const float4 zero4 = make_float4(0.f, 0.f, 0.f, 0.f);
    const int eb = half * HSTEP;           // 0 or 38

    float acc0[Q_], acc1[Q_];
    #pragma unroll
    for (int q = 0; q < Q_; q++) { acc0[q] = 0.f; acc1[q] = 0.f; }
    float dd0 = 0.f, dd1 = 0.f;

    auto fmastep = [&](const float4 a, const float4 c, int idx) {
        dd0 = fmaf(a.x,a.x, fmaf(a.y,a.y, fmaf(a.z,a.z, fmaf(a.w,a.w, dd0))));
        dd1 = fmaf(c.x,c.x, fmaf(c.y,c.y, fmaf(c.z,c.z, fmaf(c.w,c.w, dd1))));
        #pragma unroll
        for (int q = 0; q < Q_; q++) {
            float4 v = qn4[q*Q4S + idx];   // idx==75 hits zeroed pad
            acc0[q] = fmaf(a.x,v.x, fmaf(a.y,v.y, fmaf(a.z,v.z, fmaf(a.w,v.w, acc0[q]))));
            acc1[q] = fmaf(c.x,v.x, fmaf(c.y,v.y, fmaf(c.z,v.z, fmaf(c.w,v.w, acc1[q]))));
        }
    };

    float4 a = p0[eb];
    float4 c = p1[eb];
    #pragma unroll 2
    for (int j = 0; j < HSTEP-1; j++) {
        int nidx = eb + j + 1;
        float4 an = (nidx < E4) ? p0[nidx] : zero4;
        float4 cn = (nidx < E4) ? p1[nidx] : zero4;
        fmastep(a, c, eb + j);
        a = an; c = cn;
    }
    fmastep(a, c, eb + HSTEP - 1);         // upper half's last step is zero-padded

    // ---- butterfly: combine the two e-halves (lanes l and l^16) ----
    #pragma unroll
    for (int q = 0; q < Q_; q++) {
        acc0[q] += __shfl_xor_sync(0xffffffffu, acc0[q], 16);
        acc1[q] += __shfl_xor_sync(0xffffffffu, acc1[q], 16);
    }
    dd0 += __shfl_xor_sync(0xffffffffu, dd0, 16);
    dd1 += __shfl_xor_sync(0xffffffffu, dd1, 16);

    if (half == 0) {
        const float inv0 = 1.0f / (sqrtf(dd0) + 1e-9f);
        const float inv1 = 1.0f / (sqrtf(dd1) + 1e-9f);
        #pragma unroll
        for (int q = 0; q < Q_; q++) {
            s_sh[q*SSTRIDE + dpos0]      = acc0[q] * inv0;
            s_sh[q*SSTRIDE + dpos0 + 16] = acc1[q] * inv1;
        }
    }
    __syncthreads();

    // ---- RBF bank: 8 threads per q, each covers 16 docs ----
    const int myq = tid >> 3, myl = tid & 7;
    float mu_r[K_], w_r[K_];
    #pragma unroll
    for (int k = 0; k < K_; k++) {
        mu_r[k] = mus[k];
        float sg = sigmas[k];
        w_r[k] = -0.5f/(sg*sg);
    }
    float kacc[K_];
    #pragma unroll
    for (int k = 0; k < K_; k++) kacc[k] = 0.f;
    float simacc = 0.f;

    #pragma unroll 4
    for (int j = myl; j < DOCS_PER_CTA; j += 8) {
        float s = s_sh[myq*SSTRIDE + j];
        simacc += s;
        #pragma unroll
        for (int k = 0; k < K_; k++) {
            float dif = s - mu_r[k];
            kacc[k] += __expf(w_r[k]*dif*dif);
        }
    }

    #pragma unroll
    for (int k = 0; k < K_; k++) {
        float v = kacc[k];
        #pragma unroll
        for (int o = 4; o > 0; o >>= 1) v += __shfl_down_sync(0xffffffffu, v, o, 8);
        kacc[k] = v;
    }
    {
        float v = simacc;
        #pragma unroll
        for (int o = 4; o > 0; o >>= 1) v += __shfl_down_sync(0xffffffffu, v, o, 8);
        simacc = v;
    }
    if (myl == 0) {
        float* dst = &g_part[(blockIdx.x*Q_ + myq)*13];
        #pragma unroll
        for (int k = 0; k < K_; k++) dst[k] = kacc[k];
        dst[11] = simacc;
    }

    // ---- fused finalization: last CTA of this batch reduces + scores ----
    __syncthreads();
    if (tid == 0) {
        __threadfence();                       // release our partials
        int old = atomicAdd(&g_count[b], 1);
        last_flag = (old == CTAS_PER_B - 1);
    }
    __syncthreads();
    if (!last_flag) return;

    if (tid < 32) {
        __threadfence();                       // acquire other CTAs' partials
        const int lane2 = tid;
        const int q = lane2 & 15;
        const bool active = (lane2 < 16);

        float kb[K_];
        #pragma unroll
        for (int k = 0; k < K_; k++) kb[k] = 0.f;
        float sim = 0.f;
        #pragma unroll
        for (int cc = 0; cc < CTAS_PER_B; cc++) {
            const float* src = &g_part[((b*CTAS_PER_B + cc)*Q_ + q)*13];
            #pragma unroll
            for (int k = 0; k < K_; k++) kb[k] += src[k];
            sim += src[11];
        }
        const bool m = (sim != 0.0f) && active;
        float score = fc_b[0];
        #pragma unroll
        for (int k = 0; k < K_; k++) {
            float v = m ? logf(kb[k] + 1e-6f) : 0.0f;
            #pragma unroll
            for (int o = 8; o > 0; o >>= 1) v += __shfl_down_sync(0xffffffffu, v, o, 16);
            score = fmaf(v, fc_w[k], score);
        }
        if (lane2 == 0) {
            out[b] = score;
            g_count[b] = 0;                    // reset for next run / replay
        }
    }
}

extern "C" void kernel_launch(void* const* d_in, const int* in_sizes, int n_in,
                              void* d_out, int out_size)
{
    const int*   doctoks   = (const int*)  d_in[0];
    const int*   querytoks = (const int*)  d_in[1];
    // d_in[2] = query_idf (unused)
    const float* emb       = (const float*)d_in[3];
    const float* mus       = (const float*)d_in[4];
    const float* sigmas    = (const float*)d_in[5];
    const float* fc_w      = (const float*)d_in[6];
    const float* fc_b      = (const float*)d_in[7];
    float* out = (float*)d_out;

    knrm_part_kernel<<<B_*CTAS_PER_B, THREADS1>>>(
        doctoks, querytoks, emb, mus, sigmas, fc_w, fc_b, out);
}

// round 8
// speedup vs baseline: 2.3169x; 2.3169x over previous
#include <cuda_runtime.h>
#include <cuda_bf16.h>
#include <math.h>

#define B_    128
#define Q_    16
#define D_    1024
#define E_    300
#define K_    11
#define CTAS_PER_B 4
#define DOCS_PER_CTA (D_/CTAS_PER_B)   // 256
#define THREADS1 128
#define E4    (E_/4)                   // 75 float4
#define QSTRIDE 304                    // floats (76 f4)
#define SSTRIDE 264                    // mod 32 == 8 -> conflict-free 8-lane groups

// partials: [512 CTAs][16 q][13] (11 kacc + 1 simacc + pad)
__device__ float g_part[B_*CTAS_PER_B*Q_*13];
__device__ int   g_count[B_];          // zero-init; reset by last CTA each run

__global__ __launch_bounds__(THREADS1, 4)
void knrm_part_kernel(const int* __restrict__ doctoks,
                      const int* __restrict__ querytoks,
                      const float* __restrict__ emb,
                      const float* __restrict__ mus,
                      const float* __restrict__ sigmas,
                      const float* __restrict__ fc_w,
                      const float* __restrict__ fc_b,
                      float* __restrict__ out)
{
    __shared__ float sm[Q_*QSTRIDE + 16];
    __shared__ int last_flag;
    float* qn    = sm;                // 16 x 304 ; later aliased as s_sh 16 x 264
    float* tmp16 = sm + Q_*QSTRIDE;

    const int tid   = threadIdx.x;
    const int b     = blockIdx.x >> 2;
    const int cta   = blockIdx.x & 3;
    const int dbase = cta * DOCS_PER_CTA;

    // ---- load + normalize query embeddings into shared ----
    for (int i = tid; i < Q_*E_; i += THREADS1) {
        int q = i / E_, e = i - q*E_;
        int t = querytoks[b*Q_ + q];
        qn[q*QSTRIDE + e] = emb[t*E_ + e];
    }
    __syncthreads();
    {
        // 128 threads: 16 q-rows x 8 lanes each
        int q = tid >> 3, l = tid & 7;
        float ss = 0.f;
        for (int e = l; e < E_; e += 8) { float v = qn[q*QSTRIDE + e]; ss += v*v; }
        #pragma unroll
        for (int o = 4; o > 0; o >>= 1) ss += __shfl_down_sync(0xffffffffu, ss, o, 8);
        if (l == 0) tmp16[q] = 1.0f / (sqrtf(ss) + 1e-9f);
    }
    __syncthreads();
    for (int i = tid; i < Q_*E_; i += THREADS1) {
        int q = i / E_, e = i - q*E_;
        qn[q*QSTRIDE + e] *= tmp16[q];
    }
    __syncthreads();

    // ---- dot products: 2 docs/thread, rolling prefetch depth 2 ----
    const int t0 = doctoks[b*D_ + dbase + tid];
    const int t1 = doctoks[b*D_ + dbase + tid + THREADS1];
    const float4* p0 = reinterpret_cast<const float4*>(emb) + (long)t0 * E4;
    const float4* p1 = reinterpret_cast<const float4*>(emb) + (long)t1 * E4;
    const float4* qn4 = reinterpret_cast<const float4*>(qn);

    float acc0[Q_], acc1[Q_];
    #pragma unroll
    for (int q = 0; q < Q_; q++) { acc0[q] = 0.f; acc1[q] = 0.f; }
    float dd0 = 0.f, dd1 = 0.f;

    auto fmastep = [&](const float4 a, const float4 c, int e4) {
        dd0 = fmaf(a.x,a.x, fmaf(a.y,a.y, fmaf(a.z,a.z, fmaf(a.w,a.w, dd0))));
        dd1 = fmaf(c.x,c.x, fmaf(c.y,c.y, fmaf(c.z,c.z, fmaf(c.w,c.w, dd1))));
        #pragma unroll
        for (int q = 0; q < Q_; q++) {
            float4 v = qn4[q*(QSTRIDE/4) + e4];
            acc0[q] = fmaf(a.x,v.x, fmaf(a.y,v.y, fmaf(a.z,v.z, fmaf(a.w,v.w, acc0[q]))));
            acc1[q] = fmaf(c.x,v.x, fmaf(c.y,v.y, fmaf(c.z,v.z, fmaf(c.w,v.w, acc1[q]))));
        }
    };

    // depth-2 rolling prefetch; main loop j<70 has j+2<=71 < 75 (no predicates)
    float4 a0 = p0[0], c0 = p1[0];
    float4 a1 = p0[1], c1 = p1[1];
    #pragma unroll 5
    for (int j = 0; j < 70; j++) {
        float4 an = p0[j+2];
        float4 cn = p1[j+2];
        fmastep(a0, c0, j);
        a0 = a1; c0 = c1; a1 = an; c1 = cn;
    }
    #pragma unroll
    for (int j = 70; j < E4; j++) {
        float4 an, cn;
        if (j + 2 < E4) { an = p0[j+2]; cn = p1[j+2]; }
        else            { an = make_float4(0.f,0.f,0.f,0.f); cn = an; }
        fmastep(a0, c0, j);
        a0 = a1; c0 = c1; a1 = an; c1 = cn;
    }

    const float inv0 = 1.0f / (sqrtf(dd0) + 1e-9f);
    const float inv1 = 1.0f / (sqrtf(dd1) + 1e-9f);

    // ---- transpose s into shared (aliases dead qn region) ----
    float* s_sh = sm;   // 16 x 264
    __syncthreads();    // all qn reads done
    #pragma unroll
    for (int q = 0; q < Q_; q++) {
        s_sh[q*SSTRIDE + tid]            = acc0[q] * inv0;
        s_sh[q*SSTRIDE + tid + THREADS1] = acc1[q] * inv1;
    }
    __syncthreads();

    // ---- RBF bank: 8 threads per q, each covers 32 docs ----
    const int myq = tid >> 3, myl = tid & 7;
    float mu_r[K_], w_r[K_];
    #pragma unroll
    for (int k = 0; k < K_; k++) {
        mu_r[k] = mus[k];
        float sg = sigmas[k];
        w_r[k] = -0.5f/(sg*sg);
    }
    float kacc[K_];
    #pragma unroll
    for (int k = 0; k < K_; k++) kacc[k] = 0.f;
    float simacc = 0.f;

    #pragma unroll 4
    for (int j = myl; j < DOCS_PER_CTA; j += 8) {
        float s = s_sh[myq*SSTRIDE + j];
        simacc += s;
        #pragma unroll
        for (int k = 0; k < K_; k++) {
            float dif = s - mu_r[k];
            kacc[k] += __expf(w_r[k]*dif*dif);
        }
    }

    // reduce over the 8 lanes of this q-group (contiguous lanes)
    #pragma unroll
    for (int k = 0; k < K_; k++) {
        float v = kacc[k];
        #pragma unroll
        for (int o = 4; o > 0; o >>= 1) v += __shfl_down_sync(0xffffffffu, v, o, 8);
        kacc[k] = v;
    }
    {
        float v = simacc;
        #pragma unroll
        for (int o = 4; o > 0; o >>= 1) v += __shfl_down_sync(0xffffffffu, v, o, 8);
        simacc = v;
    }
    if (myl == 0) {
        float* dst = &g_part[(blockIdx.x*Q_ + myq)*13];
        #pragma unroll
        for (int k = 0; k < K_; k++) dst[k] = kacc[k];
        dst[11] = simacc;
    }

    // ---- fused finalization: last CTA of this batch reduces + scores ----
    __syncthreads();
    if (tid == 0) {
        __threadfence();                       // release our partials
        int old = atomicAdd(&g_count[b], 1);
        last_flag = (old == CTAS_PER_B - 1);
    }
    __syncthreads();
    if (!last_flag) return;

    if (tid < 32) {
        __threadfence();                       // acquire other CTAs' partials
        const int lane = tid;
        const int q = lane & 15;               // lanes 16-31 duplicate; masked below
        const bool active = (lane < 16);

        float kb[K_];
        #pragma unroll
        for (int k = 0; k < K_; k++) kb[k] = 0.f;
        float sim = 0.f;
        #pragma unroll
        for (int cc = 0; cc < CTAS_PER_B; cc++) {
            const float* src = &g_part[((b*CTAS_PER_B + cc)*Q_ + q)*13];
            #pragma unroll
            for (int k = 0; k < K_; k++) kb[k] += src[k];
            sim += src[11];
        }
        const bool m = (sim != 0.0f) && active;
        float score = fc_b[0];
        #pragma unroll
        for (int k = 0; k < K_; k++) {
            float v = m ? logf(kb[k] + 1e-6f) : 0.0f;
            #pragma unroll
            for (int o = 8; o > 0; o >>= 1) v += __shfl_down_sync(0xffffffffu, v, o, 16);
            score = fmaf(v, fc_w[k], score);
        }
        if (lane == 0) {
            out[b] = score;
            g_count[b] = 0;                    // reset for next run / replay
        }
    }
}

extern "C" void kernel_launch(void* const* d_in, const int* in_sizes, int n_in,
                              void* d_out, int out_size)
{
    const int*   doctoks   = (const int*)  d_in[0];
    const int*   querytoks = (const int*)  d_in[1];
    // d_in[2] = query_idf (unused)
    const float* emb       = (const float*)d_in[3];
    const float* mus       = (const float*)d_in[4];
    const float* sigmas    = (const float*)d_in[5];
    const float* fc_w      = (const float*)d_in[6];
    const float* fc_b      = (const float*)d_in[7];
    float* out = (float*)d_out;

    knrm_part_kernel<<<B_*CTAS_PER_B, THREADS1>>>(
        doctoks, querytoks, emb, mus, sigmas, fc_w, fc_b, out);
}